// round 5
// baseline (speedup 1.0000x reference)
#include <cuda_runtime.h>
#include <cuda_fp16.h>
#include <cstdint>

#define N_NODES 131072
#define KNBR    27
#define FIN     3
#define FOUT    32
#define NCHUNKS (N_NODES / 256)   // 512

// Scratch: h (fp16, fragment-permuted rows, 8MB), transposed indices (14MB).
__device__ __half g_h[N_NODES * FOUT];
__device__ int    g_nbrT[KNBR * N_NODES];
__device__ unsigned g_ctr;

__device__ __forceinline__ int perm32(int c) {
    return ((c >> 1) & 3) * 8 + ((c >> 3) << 1) + (c & 1);
}

__device__ __forceinline__ uint32_t f2tf32(float x) {
    uint32_t r;
    asm("cvt.rna.tf32.f32 %0, %1;" : "=r"(r) : "f"(x));
    return r;
}

__device__ __forceinline__ void mma_tf32(float d[4], const uint32_t a[4],
                                         const uint32_t b[2]) {
    asm volatile(
        "mma.sync.aligned.m16n8k8.row.col.f32.tf32.tf32.f32 "
        "{%0,%1,%2,%3}, {%4,%5,%6,%7}, {%8,%9}, {%0,%1,%2,%3};"
        : "+f"(d[0]), "+f"(d[1]), "+f"(d[2]), "+f"(d[3])
        : "r"(a[0]), "r"(a[1]), "r"(a[2]), "r"(a[3]),
          "r"(b[0]), "r"(b[1]));
}

__device__ __forceinline__ void mma_f16(float d[4],
                                        uint32_t a0, uint32_t a1, uint32_t a2, uint32_t a3,
                                        uint32_t b0, uint32_t b1) {
    asm volatile(
        "mma.sync.aligned.m16n8k16.row.col.f32.f16.f16.f32 "
        "{%0,%1,%2,%3}, {%4,%5,%6,%7}, {%8,%9}, {%0,%1,%2,%3};"
        : "+f"(d[0]), "+f"(d[1]), "+f"(d[2]), "+f"(d[3])
        : "r"(a0), "r"(a1), "r"(a2), "r"(a3), "r"(b0), "r"(b1));
}

// ---------------------------------------------------------------------------
// Pre-pass A: reset the work-stealing counter.
__global__ void reset_ctr_kernel() { g_ctr = 0; }

// Pre-pass B: transpose nbr[n][k] -> g_nbrT[k][n] (tiled via smem).
__global__ __launch_bounds__(256) void transpose_nbr_kernel(const int* __restrict__ nbr)
{
    __shared__ int tile[64 * KNBR];
    const int nb = blockIdx.x * 64;
    for (int i = threadIdx.x; i < 64 * KNBR; i += 256)
        tile[i] = nbr[nb * KNBR + i];
    __syncthreads();
    for (int j = threadIdx.x; j < KNBR * 64; j += 256) {
        int k = j >> 6, n = j & 63;
        g_nbrT[k * N_NODES + nb + n] = tile[n * KNBR + k];
    }
}

// ---------------------------------------------------------------------------
// Stage 1: h = BN+SiLU( sum_k x[nbrT[k][n]] @ w1[k] ), tf32 mma, fp16 permuted
// output via per-warp smem transpose. One 256-node chunk per CTA, grid=512.
// ---------------------------------------------------------------------------
#define S1_W1    0
#define S1_SC    (KNBR * 32 * 4 * 4)          // 13824
#define S1_SH    (S1_SC + 128)
#define S1_BUF   (S1_SH + 128)                // 14080
#define S1_SMEM  (S1_BUF + 8 * 2048)          // 30464

__global__ __launch_bounds__(256) void stage1_kernel(
    const float* __restrict__ x,
    const float* __restrict__ w1,
    const float* __restrict__ bg, const float* __restrict__ bb,
    const float* __restrict__ bm, const float* __restrict__ bv)
{
    extern __shared__ char smem[];
    uint32_t* w1s = (uint32_t*)(smem + S1_W1);
    float*    sc  = (float*)(smem + S1_SC);
    float*    sh  = (float*)(smem + S1_SH);

    const int tid = threadIdx.x;

    for (int i = tid; i < KNBR * 32 * 4; i += 256) {
        int k = i >> 7, o = (i >> 2) & 31, c = i & 3;
        float v = (c < FIN) ? w1[(k * FIN + c) * FOUT + o] : 0.0f;
        w1s[i] = f2tf32(v);
    }
    if (tid < 32) {
        float s = bg[tid] * rsqrtf(bv[tid] + 1e-5f);
        sc[tid] = s;
        sh[tid] = bb[tid] - bm[tid] * s;
    }
    __syncthreads();

    const int warp = tid >> 5, lane = tid & 31;
    const int g = lane >> 2, c4 = lane & 3;
    const int nb = blockIdx.x * 256 + warp * 32;
    __half* buf = (__half*)(smem + S1_BUF) + warp * 1024;

    float acc[2][4][4];
    #pragma unroll
    for (int t = 0; t < 2; t++)
        #pragma unroll
        for (int nf = 0; nf < 4; nf++)
            #pragma unroll
            for (int i = 0; i < 4; i++) acc[t][nf][i] = 0.0f;

    int I[4];
    float X0[4], X1[4];

#define LOADI1(kk) { const int* p = g_nbrT + (size_t)(kk) * N_NODES + nb; \
    I[0] = p[g]; I[1] = p[8 + g]; I[2] = p[16 + g]; I[3] = p[24 + g]; }
#define LOADX(XB) { \
    _Pragma("unroll") \
    for (int j = 0; j < 4; j++) \
        XB[j] = (c4 < FIN) ? __ldg(x + I[j] * FIN + c4) : 0.0f; }
#define COMP1(kk, XB) { \
    uint32_t b0f[4]; \
    _Pragma("unroll") \
    for (int nf = 0; nf < 4; nf++) \
        b0f[nf] = w1s[(((kk) * 32 + nf * 8 + g) << 2) + c4]; \
    _Pragma("unroll") \
    for (int t = 0; t < 2; t++) { \
        uint32_t a[4]; \
        a[0] = f2tf32(XB[2 * t]); a[1] = f2tf32(XB[2 * t + 1]); \
        a[2] = 0u; a[3] = 0u; \
        _Pragma("unroll") \
        for (int nf = 0; nf < 4; nf++) { \
            uint32_t b[2] = { b0f[nf], 0u }; \
            mma_tf32(acc[t][nf], a, b); \
        } } }

    LOADI1(0); LOADX(X0); LOADI1(1);
    #pragma unroll 1
    for (int k = 0; k < KNBR - 2; k += 2) {
        LOADX(X1); LOADI1(k + 2);
        COMP1(k, X0);
        LOADX(X0); if (k + 3 < KNBR) LOADI1(k + 3);
        COMP1(k + 1, X1);
    }
    COMP1(KNBR - 1, X0);
#undef LOADI1
#undef LOADX
#undef COMP1

    // BN + SiLU -> fp16 permuted smem tile -> coalesced 16B stores.
    #pragma unroll
    for (int t = 0; t < 2; t++)
        #pragma unroll
        for (int nf = 0; nf < 4; nf++)
            #pragma unroll
            for (int i = 0; i < 4; i++) {
                int o  = nf * 8 + 2 * c4 + (i & 1);
                int nl = t * 16 + g + ((i >> 1) << 3);
                float v = acc[t][nf][i] * sc[o] + sh[o];
                float s = v * (1.0f / (1.0f + __expf(-v)));
                buf[nl * 32 + perm32(o)] = __float2half_rn(s);
            }
    __syncwarp();
    uint4* dst = (uint4*)(g_h + (size_t)nb * FOUT);
    const uint4* src = (const uint4*)buf;
    #pragma unroll
    for (int m = 0; m < 4; m++) dst[m * 32 + lane] = src[m * 32 + lane];
}

// ---------------------------------------------------------------------------
// Stage 2: fp16 m16n8k16 gather-GEMM over g_h + point branch + fused output.
// 256-thread CTAs, 3/SM (85-reg cap), no block barriers in the hot loop,
// chunks claimed via atomic work-stealing counter.
// ---------------------------------------------------------------------------
#define S2_W2   0
#define S2_MW   (KNBR * 32 * 32 * 2)      // 55296
#define S2_PA   (S2_MW + 96 * 4)          // 55680
#define S2_PB   (S2_PA + 128)             // 55808
#define S2_CHK  (S2_PB + 128)             // 55936
#define S2_SMEM (S2_CHK + 16)             // 55952

__global__ __launch_bounds__(256, 3) void stage2_kernel(
    const float* __restrict__ w2,
    const float* __restrict__ zf,
    const float* __restrict__ mlpw, const float* __restrict__ mlpb,
    const float* __restrict__ mg, const float* __restrict__ mb2,
    const float* __restrict__ mm, const float* __restrict__ mv,
    float* __restrict__ out)
{
    extern __shared__ char smem[];
    __half*    w2h   = (__half*)(smem + S2_W2);
    float*     mw_s  = (float*)(smem + S2_MW);
    float*     pA    = (float*)(smem + S2_PA);
    float*     pB    = (float*)(smem + S2_PB);
    unsigned*  schk  = (unsigned*)(smem + S2_CHK);

    const int tid = threadIdx.x;

    for (int i = tid; i < KNBR * FOUT * FOUT; i += 256) {
        int k = i >> 10, c = (i >> 5) & 31, o = i & 31;
        w2h[(k * 32 + o) * 32 + perm32(c)] = __float2half_rn(__ldg(w2 + i));
    }
    for (int i = tid; i < FIN * FOUT; i += 256) mw_s[i] = mlpw[i];
    if (tid < 32) {
        float s = mg[tid] * rsqrtf(mv[tid] + 1e-5f);
        pA[tid] = s;
        pB[tid] = mlpb[tid] * s + mb2[tid] - mm[tid] * s;
    }

    const uint4* h4  = (const uint4*)g_h;
    const uint4* w2v = (const uint4*)w2h;
    const int warp = tid >> 5, lane = tid & 31;
    const int g = lane >> 2, c4 = lane & 3;

#define LOADI2(kk) { const int* p = g_nbrT + (size_t)(kk) * N_NODES + nb; \
    I[0] = p[g]; I[1] = p[8 + g]; I[2] = p[16 + g]; I[3] = p[24 + g]; }
#define LOADA(AB) { \
    AB[0] = h4[I[0] * 4 + c4]; AB[1] = h4[I[1] * 4 + c4]; \
    AB[2] = h4[I[2] * 4 + c4]; AB[3] = h4[I[3] * 4 + c4]; }
#define COMP2(kk, AB) { \
    uint4 W[4]; \
    _Pragma("unroll") \
    for (int nf = 0; nf < 4; nf++) \
        W[nf] = w2v[(((kk) * 32 + nf * 8 + g) << 2) + c4]; \
    _Pragma("unroll") \
    for (int t = 0; t < 2; t++) { \
        _Pragma("unroll") \
        for (int nf = 0; nf < 4; nf++) { \
            mma_f16(acc[t][nf], AB[2*t].x, AB[2*t+1].x, AB[2*t].y, AB[2*t+1].y, \
                    W[nf].x, W[nf].y); \
            mma_f16(acc[t][nf], AB[2*t].z, AB[2*t+1].z, AB[2*t].w, AB[2*t+1].w, \
                    W[nf].z, W[nf].w); \
        } } }

    while (true) {
        __syncthreads();                 // also covers w2h init on first pass
        if (tid == 0) *schk = atomicAdd(&g_ctr, 1u);
        __syncthreads();
        unsigned chunk = *schk;
        if (chunk >= NCHUNKS) break;

        const int nb = (int)chunk * 256 + warp * 32;

        float acc[2][4][4];
        #pragma unroll
        for (int t = 0; t < 2; t++)
            #pragma unroll
            for (int nf = 0; nf < 4; nf++)
                #pragma unroll
                for (int i = 0; i < 4; i++) acc[t][nf][i] = 0.0f;

        int I[4];
        uint4 A0[4], A1[4];
        LOADI2(0); LOADA(A0); LOADI2(1);
        #pragma unroll 1
        for (int k = 0; k < KNBR - 2; k += 2) {
            LOADA(A1); LOADI2(k + 2);
            COMP2(k, A0);
            LOADA(A0); if (k + 3 < KNBR) LOADI2(k + 3);
            COMP2(k + 1, A1);
        }
        COMP2(KNBR - 1, A0);

        // Epilogue: point branch + fuse; write both output copies.
        #pragma unroll
        for (int t = 0; t < 2; t++) {
            int n0 = nb + t * 16 + g;
            float z00 = zf[n0 * 3], z01 = zf[n0 * 3 + 1], z02 = zf[n0 * 3 + 2];
            float z10 = zf[(n0 + 8) * 3], z11 = zf[(n0 + 8) * 3 + 1], z12 = zf[(n0 + 8) * 3 + 2];
            #pragma unroll
            for (int nf = 0; nf < 4; nf++) {
                int o0 = nf * 8 + 2 * c4;
                float w0a = mw_s[o0],     w1a = mw_s[32 + o0],     w2a = mw_s[64 + o0];
                float w0b = mw_s[o0 + 1], w1b = mw_s[32 + o0 + 1], w2b = mw_s[64 + o0 + 1];
                float sA0 = pA[o0], sB0 = pB[o0], sA1 = pA[o0 + 1], sB1 = pB[o0 + 1];

                float d0 = z00 * w0a + z01 * w1a + z02 * w2a;
                float d1 = z00 * w0b + z01 * w1b + z02 * w2b;
                float e0 = z10 * w0a + z11 * w1a + z12 * w2a;
                float e1 = z10 * w0b + z11 * w1b + z12 * w2b;

                float2 lo, hi;
                lo.x = acc[t][nf][0] + fmaxf(d0 * sA0 + sB0, 0.0f);
                lo.y = acc[t][nf][1] + fmaxf(d1 * sA1 + sB1, 0.0f);
                hi.x = acc[t][nf][2] + fmaxf(e0 * sA0 + sB0, 0.0f);
                hi.y = acc[t][nf][3] + fmaxf(e1 * sA1 + sB1, 0.0f);

                size_t half = (size_t)N_NODES * FOUT;
                *(float2*)(out + (size_t)n0 * FOUT + o0)              = lo;
                *(float2*)(out + half + (size_t)n0 * FOUT + o0)       = lo;
                *(float2*)(out + (size_t)(n0 + 8) * FOUT + o0)        = hi;
                *(float2*)(out + half + (size_t)(n0 + 8) * FOUT + o0) = hi;
            }
        }
    }
#undef LOADI2
#undef LOADA
#undef COMP2
}

// ---------------------------------------------------------------------------

extern "C" void kernel_launch(void* const* d_in, const int* in_sizes, int n_in,
                              void* d_out, int out_size) {
    (void)in_sizes; (void)n_in; (void)out_size;
    const float* x    = (const float*)d_in[0];
    const float* z    = (const float*)d_in[1];
    const int*   nbr  = (const int*)  d_in[2];
    const float* w1   = (const float*)d_in[3];
    const float* bg   = (const float*)d_in[4];
    const float* bb   = (const float*)d_in[5];
    const float* bm   = (const float*)d_in[6];
    const float* bv   = (const float*)d_in[7];
    const float* w2   = (const float*)d_in[8];
    const float* mlpw = (const float*)d_in[9];
    const float* mlpb = (const float*)d_in[10];
    const float* mg   = (const float*)d_in[11];
    const float* mb2  = (const float*)d_in[12];
    const float* mm   = (const float*)d_in[13];
    const float* mv   = (const float*)d_in[14];
    float* out = (float*)d_out;

    cudaFuncSetAttribute(stage1_kernel, cudaFuncAttributeMaxDynamicSharedMemorySize, S1_SMEM);
    cudaFuncSetAttribute(stage2_kernel, cudaFuncAttributeMaxDynamicSharedMemorySize, S2_SMEM);

    reset_ctr_kernel<<<1, 1>>>();
    transpose_nbr_kernel<<<N_NODES / 64, 256>>>(nbr);
    stage1_kernel<<<NCHUNKS, 256, S1_SMEM>>>(x, w1, bg, bb, bm, bv);
    stage2_kernel<<<444, 256, S2_SMEM>>>(w2, z, mlpw, mlpb, mg, mb2, mm, mv, out);
}

// round 6
// speedup vs baseline: 1.2518x; 1.2518x over previous
#include <cuda_runtime.h>
#include <cuda_fp16.h>
#include <cstdint>

#define N_NODES 131072
#define KNBR    27
#define FIN     3
#define FOUT    32
#define CHUNK   256
#define NCHUNKS (N_NODES / CHUNK)   // 512

// 8 MB scratch: intermediate h (post BN+SiLU), fp16, fragment-permuted rows:
// g_h[n*32 + perm32(c)] = h[n][c] => lane c4 reads its whole m16n8k16 A-slice
// of a row as ONE contiguous 16B chunk at byte offset c4*16 of the 64B row.
__device__ __half g_h[N_NODES * FOUT];
__device__ unsigned g_ctr;

__device__ __forceinline__ int perm32(int c) {
    return ((c >> 1) & 3) * 8 + ((c >> 3) << 1) + (c & 1);
}

__device__ __forceinline__ uint32_t f2tf32(float x) {
    uint32_t r;
    asm("cvt.rna.tf32.f32 %0, %1;" : "=r"(r) : "f"(x));
    return r;
}

__device__ __forceinline__ void mma_tf32(float d[4], const uint32_t a[4],
                                         const uint32_t b[2]) {
    asm volatile(
        "mma.sync.aligned.m16n8k8.row.col.f32.tf32.tf32.f32 "
        "{%0,%1,%2,%3}, {%4,%5,%6,%7}, {%8,%9}, {%0,%1,%2,%3};"
        : "+f"(d[0]), "+f"(d[1]), "+f"(d[2]), "+f"(d[3])
        : "r"(a[0]), "r"(a[1]), "r"(a[2]), "r"(a[3]),
          "r"(b[0]), "r"(b[1]));
}

__device__ __forceinline__ void mma_f16(float d[4],
                                        uint32_t a0, uint32_t a1, uint32_t a2, uint32_t a3,
                                        uint32_t b0, uint32_t b1) {
    asm volatile(
        "mma.sync.aligned.m16n8k16.row.col.f32.f16.f16.f32 "
        "{%0,%1,%2,%3}, {%4,%5,%6,%7}, {%8,%9}, {%0,%1,%2,%3};"
        : "+f"(d[0]), "+f"(d[1]), "+f"(d[2]), "+f"(d[3])
        : "r"(a0), "r"(a1), "r"(a2), "r"(a3), "r"(b0), "r"(b1));
}

__global__ void reset_ctr_kernel() { g_ctr = 0; }

// ---------------------------------------------------------------------------
// Stage 1: h = BN+SiLU( sum_k x[nbr[n,k]] @ w1[k] ), tf32 mma (K 3->8 pad).
// 512 threads, one 256-node chunk per CTA (grid=512). Warp owns 16 nodes.
// Epilogue: per-warp smem transpose -> fp16 permuted g_h, coalesced STG.128.
// ---------------------------------------------------------------------------
#define S1_NBR   0
#define S1_W1    (CHUNK * KNBR * 4)               // 27648
#define S1_SC    (S1_W1 + KNBR * 32 * 4 * 4)      // +13824 = 41472
#define S1_SH    (S1_SC + 128)
#define S1_BUF   (S1_SH + 128)                    // 41728, 16B aligned
#define S1_SMEM  (S1_BUF + 16 * 1024)             // 58112

__global__ __launch_bounds__(512, 2) void stage1_kernel(
    const float* __restrict__ x, const int* __restrict__ nbr,
    const float* __restrict__ w1,
    const float* __restrict__ bg, const float* __restrict__ bb,
    const float* __restrict__ bm, const float* __restrict__ bv)
{
    extern __shared__ char smem[];
    int*      nbr_s = (int*)(smem + S1_NBR);
    uint32_t* w1s   = (uint32_t*)(smem + S1_W1);
    float*    sc    = (float*)(smem + S1_SC);
    float*    sh    = (float*)(smem + S1_SH);

    const int tid = threadIdx.x;
    const int nbase = blockIdx.x * CHUNK;

    for (int i = tid; i < KNBR * 32 * 4; i += 512) {
        int k = i >> 7, o = (i >> 2) & 31, c = i & 3;
        float v = (c < FIN) ? w1[(k * FIN + c) * FOUT + o] : 0.0f;
        w1s[i] = f2tf32(v);
    }
    for (int i = tid; i < CHUNK * KNBR; i += 512)
        nbr_s[i] = nbr[nbase * KNBR + i];
    if (tid < 32) {
        float s = bg[tid] * rsqrtf(bv[tid] + 1e-5f);
        sc[tid] = s;
        sh[tid] = bb[tid] - bm[tid] * s;
    }
    __syncthreads();

    const int warp = tid >> 5, lane = tid & 31;
    const int g = lane >> 2, c4 = lane & 3;
    __half* buf = (__half*)(smem + S1_BUF) + warp * 512;

    float acc[4][4];
    #pragma unroll
    for (int nf = 0; nf < 4; nf++)
        #pragma unroll
        for (int i = 0; i < 4; i++) acc[nf][i] = 0.0f;

    float X0[2], X1[2];

#define LOADX1(kk, XB) { \
    int r0 = nbr_s[(warp * 16 + g) * KNBR + (kk)]; \
    int r1 = nbr_s[(warp * 16 + 8 + g) * KNBR + (kk)]; \
    XB[0] = (c4 < FIN) ? __ldg(x + r0 * FIN + c4) : 0.0f; \
    XB[1] = (c4 < FIN) ? __ldg(x + r1 * FIN + c4) : 0.0f; }
#define COMP1(kk, XB) { \
    uint32_t a[4]; \
    a[0] = f2tf32(XB[0]); a[1] = f2tf32(XB[1]); a[2] = 0u; a[3] = 0u; \
    _Pragma("unroll") \
    for (int nf = 0; nf < 4; nf++) { \
        uint32_t b[2] = { w1s[(((kk) * 32 + nf * 8 + g) << 2) + c4], 0u }; \
        mma_tf32(acc[nf], a, b); \
    } }

    LOADX1(0, X0);
    #pragma unroll 1
    for (int k = 0; k < KNBR - 1; k += 2) {
        LOADX1(k + 1, X1);
        COMP1(k, X0);
        if (k + 2 < KNBR) LOADX1(k + 2, X0);
        COMP1(k + 1, X1);
    }
    COMP1(KNBR - 1, X0);
#undef LOADX1
#undef COMP1

    // BN + SiLU -> fp16 permuted smem tile -> coalesced 16B stores.
    #pragma unroll
    for (int nf = 0; nf < 4; nf++)
        #pragma unroll
        for (int i = 0; i < 4; i++) {
            int o  = nf * 8 + 2 * c4 + (i & 1);
            int nl = g + ((i >> 1) << 3);
            float v = acc[nf][i] * sc[o] + sh[o];
            float s = v * (1.0f / (1.0f + __expf(-v)));
            buf[nl * 32 + perm32(o)] = __float2half_rn(s);
        }
    __syncwarp();
    uint4* dst = (uint4*)(g_h + (size_t)(nbase + warp * 16) * FOUT);
    const uint4* src = (const uint4*)buf;
    dst[lane] = src[lane];
    dst[32 + lane] = src[32 + lane];
}

// ---------------------------------------------------------------------------
// Stage 2: fp16 m16n8k16 gather-GEMM over g_h + point branch + fused output.
// 512 threads, 2 CTAs/SM (64-reg cap). Warp owns 16 nodes; chunk = 256 nodes;
// nbr staged in smem (index LDS, not a dependent global chain); chunks via
// atomic work-stealing. w2 in smem, fragment-permuted: 4 conflict-free
// LDS.128 per (k, o-tile); A gathers are 1 LDG.128 per row (64B rows).
// ---------------------------------------------------------------------------
#define S2_NBR  0
#define S2_W2   (CHUNK * KNBR * 4)            // 27648 (16B aligned)
#define S2_MW   (S2_W2 + KNBR * 32 * 32 * 2)  // +55296 = 82944
#define S2_PA   (S2_MW + 96 * 4)              // 83328
#define S2_PB   (S2_PA + 128)                 // 83456
#define S2_CHK  (S2_PB + 128)                 // 83584
#define S2_SMEM (S2_CHK + 16)                 // 83600

__global__ __launch_bounds__(512, 2) void stage2_kernel(
    const int* __restrict__ nbr,
    const float* __restrict__ w2,
    const float* __restrict__ zf,
    const float* __restrict__ mlpw, const float* __restrict__ mlpb,
    const float* __restrict__ mg, const float* __restrict__ mb2,
    const float* __restrict__ mm, const float* __restrict__ mv,
    float* __restrict__ out)
{
    extern __shared__ char smem[];
    int*       nbr_s = (int*)(smem + S2_NBR);
    __half*    w2h   = (__half*)(smem + S2_W2);
    float*     mw_s  = (float*)(smem + S2_MW);
    float*     pA    = (float*)(smem + S2_PA);
    float*     pB    = (float*)(smem + S2_PB);
    unsigned*  schk  = (unsigned*)(smem + S2_CHK);

    const int tid = threadIdx.x;

    for (int i = tid; i < KNBR * FOUT * FOUT; i += 512) {
        int k = i >> 10, c = (i >> 5) & 31, o = i & 31;
        w2h[(k * 32 + o) * 32 + perm32(c)] = __float2half_rn(__ldg(w2 + i));
    }
    for (int i = tid; i < FIN * FOUT; i += 512) mw_s[i] = mlpw[i];
    if (tid < 32) {
        float s = mg[tid] * rsqrtf(mv[tid] + 1e-5f);
        pA[tid] = s;
        pB[tid] = mlpb[tid] * s + mb2[tid] - mm[tid] * s;
    }

    const uint4* h4  = (const uint4*)g_h;
    const uint4* w2v = (const uint4*)w2h;
    const int warp = tid >> 5, lane = tid & 31;
    const int g = lane >> 2, c4 = lane & 3;

#define LOADA(kk, AB) { \
    int r0 = nbr_s[(warp * 16 + g) * KNBR + (kk)]; \
    int r1 = nbr_s[(warp * 16 + 8 + g) * KNBR + (kk)]; \
    AB[0] = h4[r0 * 4 + c4]; \
    AB[1] = h4[r1 * 4 + c4]; }
#define COMP2(kk, AB) { \
    _Pragma("unroll") \
    for (int nf = 0; nf < 4; nf++) { \
        uint4 W = w2v[(((kk) * 32 + nf * 8 + g) << 2) + c4]; \
        mma_f16(acc[nf], AB[0].x, AB[1].x, AB[0].y, AB[1].y, W.x, W.y); \
        mma_f16(acc[nf], AB[0].z, AB[1].z, AB[0].w, AB[1].w, W.z, W.w); \
    } }

    while (true) {
        __syncthreads();                 // also orders w2h init / nbr_s reuse
        if (tid == 0) *schk = atomicAdd(&g_ctr, 1u);
        __syncthreads();
        unsigned chunk = *schk;
        if (chunk >= NCHUNKS) break;

        const int nbase = (int)chunk * CHUNK;
        for (int i = tid; i < CHUNK * KNBR; i += 512)
            nbr_s[i] = nbr[nbase * KNBR + i];
        __syncthreads();

        float acc[4][4];
        #pragma unroll
        for (int nf = 0; nf < 4; nf++)
            #pragma unroll
            for (int i = 0; i < 4; i++) acc[nf][i] = 0.0f;

        uint4 A0[2], A1[2];
        LOADA(0, A0);
        #pragma unroll 1
        for (int k = 0; k < KNBR - 1; k += 2) {
            LOADA(k + 1, A1);
            COMP2(k, A0);
            if (k + 2 < KNBR) LOADA(k + 2, A0);
            COMP2(k + 1, A1);
        }
        COMP2(KNBR - 1, A0);

        // Epilogue: point branch + fuse; write both output copies.
        {
            int n0 = nbase + warp * 16 + g;
            float z00 = zf[n0 * 3], z01 = zf[n0 * 3 + 1], z02 = zf[n0 * 3 + 2];
            float z10 = zf[(n0 + 8) * 3], z11 = zf[(n0 + 8) * 3 + 1], z12 = zf[(n0 + 8) * 3 + 2];
            #pragma unroll
            for (int nf = 0; nf < 4; nf++) {
                int o0 = nf * 8 + 2 * c4;
                float w0a = mw_s[o0],     w1a = mw_s[32 + o0],     w2a = mw_s[64 + o0];
                float w0b = mw_s[o0 + 1], w1b = mw_s[32 + o0 + 1], w2b = mw_s[64 + o0 + 1];
                float sA0 = pA[o0], sB0 = pB[o0], sA1 = pA[o0 + 1], sB1 = pB[o0 + 1];

                float d0 = z00 * w0a + z01 * w1a + z02 * w2a;
                float d1 = z00 * w0b + z01 * w1b + z02 * w2b;
                float e0 = z10 * w0a + z11 * w1a + z12 * w2a;
                float e1 = z10 * w0b + z11 * w1b + z12 * w2b;

                float2 lo, hi;
                lo.x = acc[nf][0] + fmaxf(d0 * sA0 + sB0, 0.0f);
                lo.y = acc[nf][1] + fmaxf(d1 * sA1 + sB1, 0.0f);
                hi.x = acc[nf][2] + fmaxf(e0 * sA0 + sB0, 0.0f);
                hi.y = acc[nf][3] + fmaxf(e1 * sA1 + sB1, 0.0f);

                size_t half = (size_t)N_NODES * FOUT;
                *(float2*)(out + (size_t)n0 * FOUT + o0)              = lo;
                *(float2*)(out + half + (size_t)n0 * FOUT + o0)       = lo;
                *(float2*)(out + (size_t)(n0 + 8) * FOUT + o0)        = hi;
                *(float2*)(out + half + (size_t)(n0 + 8) * FOUT + o0) = hi;
            }
        }
    }
#undef LOADA
#undef COMP2
}

// ---------------------------------------------------------------------------

extern "C" void kernel_launch(void* const* d_in, const int* in_sizes, int n_in,
                              void* d_out, int out_size) {
    (void)in_sizes; (void)n_in; (void)out_size;
    const float* x    = (const float*)d_in[0];
    const float* z    = (const float*)d_in[1];
    const int*   nbr  = (const int*)  d_in[2];
    const float* w1   = (const float*)d_in[3];
    const float* bg   = (const float*)d_in[4];
    const float* bb   = (const float*)d_in[5];
    const float* bm   = (const float*)d_in[6];
    const float* bv   = (const float*)d_in[7];
    const float* w2   = (const float*)d_in[8];
    const float* mlpw = (const float*)d_in[9];
    const float* mlpb = (const float*)d_in[10];
    const float* mg   = (const float*)d_in[11];
    const float* mb2  = (const float*)d_in[12];
    const float* mm   = (const float*)d_in[13];
    const float* mv   = (const float*)d_in[14];
    float* out = (float*)d_out;

    cudaFuncSetAttribute(stage1_kernel, cudaFuncAttributeMaxDynamicSharedMemorySize, S1_SMEM);
    cudaFuncSetAttribute(stage2_kernel, cudaFuncAttributeMaxDynamicSharedMemorySize, S2_SMEM);

    reset_ctr_kernel<<<1, 1>>>();
    stage1_kernel<<<NCHUNKS, 512, S1_SMEM>>>(x, nbr, w1, bg, bb, bm, bv);
    stage2_kernel<<<296, 512, S2_SMEM>>>(nbr, w2, z, mlpw, mlpb, mg, mb2, mm, mv, out);
}